// round 16
// baseline (speedup 1.0000x reference)
#include <cuda_runtime.h>
#include <cuda_fp16.h>
#include <cstdint>

// ---------------------------------------------------------------------------
// Upsampling_77214922047593 — legacy mma.sync fp16 single-pass (sm_103 base).
//   fused12:  h2 = unary(unary(support @ W1) @ W2)   65536 rows (h1 in smem)
//   layer3:   out = unary((gather(h2)+query) @ W3)   262144 rows
// R15->R16: both GEMM kernels become PERSISTENT at the proven 2-CTA/SM
// geometry (grid=304, stride loop over row blocks; inner loops unchanged).
// Amortizes per-CTA prologue (idx loads, pipeline prime, exposed first-A
// DRAM latency) over 13.5 / 3.4 blocks and removes wave-transition gaps.
// layer3 gather indices held in registers (s_grow smem + barrier dropped).
// ---------------------------------------------------------------------------

namespace {
constexpr int Mm   = 16384;
constexpr int CIN  = 512;
constexpr int COUT = 256;
constexpr float EPSv   = 1e-5f;
constexpr float SLOPEv = 0.1f;

constexpr int ROWS12 = 65536;
constexpr int ROWS3  = 262144;

constexpr int GRID_P = 304;        // 152 SMs x 2 CTAs

// ---- fused12 geometry (TILE 64x256, KC=32, 2 CTAs/SM) ----
constexpr int TM12   = 64;
constexpr int KC12   = 32;
constexpr int AST12  = 40;                       // fp16 elems (80B rows)
constexpr int A1B    = TM12 * AST12 * 2;         // 5120
constexpr int B12B   = COUT * AST12 * 2;         // 20480
constexpr int A2OFF  = 2 * A1B + 2 * B12B;       // 51200
constexpr size_t SMEM_F = A2OFF + 8 * A1B;       // 92160 (x2 CTAs = 184320)
constexpr int NBLK12 = ROWS12 / TM12;            // 1024

// ---- layer3 geometry (TILE 64x256, KC=64, 2 CTAs/SM) ----
constexpr int TILE_M3 = 64;
constexpr int KC3     = 64;
constexpr int ASTRE   = 72;                      // fp16 elems (144B rows)
constexpr int A3_BYTES = TILE_M3 * ASTRE * 2;    // 9216
constexpr int B3_BYTES = COUT * ASTRE * 2;       // 36864
constexpr int BUF3     = A3_BYTES + B3_BYTES;    // 46080
constexpr size_t SMEM_3 = 2 * (size_t)BUF3;      // 92160
constexpr int NBLK3 = ROWS3 / TILE_M3;           // 4096
} // namespace

__device__ __half g_h2f[(size_t)ROWS12 * COUT];     // fp16 h2 (32 MB)
__device__ __half g_Wth[3][COUT][CIN];              // rounded, transposed weights

// ---------------- helpers ----------------
__device__ __forceinline__ uint32_t smem_u32(const void* p) {
    uint32_t a;
    asm("{ .reg .u64 t; cvta.to.shared.u64 t, %1; cvt.u32.u64 %0, t; }"
        : "=r"(a) : "l"(p));
    return a;
}

#define LDSM4(r, addr)                                                         \
    asm volatile("ldmatrix.sync.aligned.m8n8.x4.shared.b16 {%0,%1,%2,%3}, [%4];" \
        : "=r"((r)[0]), "=r"((r)[1]), "=r"((r)[2]), "=r"((r)[3]) : "r"(addr))

#define MMA_F16(c, a, b0, b1)                                                  \
    asm volatile("mma.sync.aligned.m16n8k16.row.col.f32.f16.f16.f32 "          \
        "{%0,%1,%2,%3}, {%4,%5,%6,%7}, {%8,%9}, {%0,%1,%2,%3};"                \
        : "+f"((c)[0]), "+f"((c)[1]), "+f"((c)[2]), "+f"((c)[3])               \
        : "r"((a)[0]), "r"((a)[1]), "r"((a)[2]), "r"((a)[3]),                  \
          "r"(b0), "r"(b1))

#define CP_ASYNC16CG(dst, src)                                                 \
    asm volatile("cp.async.cg.shared.global [%0], [%1], 16;"                   \
        :: "r"(dst), "l"(src))
#define CP_COMMIT() asm volatile("cp.async.commit_group;" ::: "memory")
#define CP_WAIT0()  asm volatile("cp.async.wait_group 0;" ::: "memory")

__device__ __forceinline__ void round4h(float4 v, uint32_t h[2]) {
    __half2 h01 = __floats2half2_rn(v.x, v.y);
    __half2 h23 = __floats2half2_rn(v.z, v.w);
    h[0] = *reinterpret_cast<uint32_t*>(&h01);
    h[1] = *reinterpret_cast<uint32_t*>(&h23);
}

// GroupNorm-of-8 + affine + leaky-relu on one n8 tile's 4 acc values.
__device__ __forceinline__ void gn8(float v0, float v1, float v2, float v3,
                                    float2 gg, float2 be,
                                    float& y0, float& y1, float& y2, float& y3)
{
    float s0 = v0 + v1,           s1 = v2 + v3;
    float t0 = v0 * v0 + v1 * v1, t1 = v2 * v2 + v3 * v3;
    s0 += __shfl_xor_sync(0xffffffffu, s0, 1);
    s0 += __shfl_xor_sync(0xffffffffu, s0, 2);
    s1 += __shfl_xor_sync(0xffffffffu, s1, 1);
    s1 += __shfl_xor_sync(0xffffffffu, s1, 2);
    t0 += __shfl_xor_sync(0xffffffffu, t0, 1);
    t0 += __shfl_xor_sync(0xffffffffu, t0, 2);
    t1 += __shfl_xor_sync(0xffffffffu, t1, 1);
    t1 += __shfl_xor_sync(0xffffffffu, t1, 2);
    const float m0 = s0 * 0.125f, m1 = s1 * 0.125f;
    const float r0 = rsqrtf(fmaxf(t0 * 0.125f - m0 * m0, 0.f) + EPSv);
    const float r1 = rsqrtf(fmaxf(t1 * 0.125f - m1 * m1, 0.f) + EPSv);
    y0 = (v0 - m0) * r0 * gg.x + be.x;
    y1 = (v1 - m0) * r0 * gg.y + be.y;
    y2 = (v2 - m1) * r1 * gg.x + be.x;
    y3 = (v3 - m1) * r1 * gg.y + be.y;
    y0 = (y0 >= 0.f) ? y0 : SLOPEv * y0;
    y1 = (y1 >= 0.f) ? y1 : SLOPEv * y1;
    y2 = (y2 >= 0.f) ? y2 : SLOPEv * y2;
    y3 = (y3 >= 0.f) ? y3 : SLOPEv * y3;
}

// ---------------- weight prologue: coalesced smem-tile transpose -----------
__global__ void split_w_all(const float* __restrict__ W1,
                            const float* __restrict__ W2,
                            const float* __restrict__ W3)
{
    __shared__ __half tile[32][33];
    int b = blockIdx.x;            // 0..255
    const float* W;
    int layer, kt, nt;
    if (b < 128)      { W = W1; layer = 0; kt = b >> 3;        nt = b & 7; }
    else if (b < 192) { W = W2; layer = 1; kt = (b - 128) >> 3; nt = b & 7; }
    else              { W = W3; layer = 2; kt = (b - 192) >> 3; nt = b & 7; }

    const int tx = threadIdx.x & 31;
    const int ty = threadIdx.x >> 5;   // 0..7

#pragma unroll
    for (int r = 0; r < 4; r++) {
        int k = kt * 32 + ty + r * 8;
        int n = nt * 32 + tx;
        tile[ty + r * 8][tx] = __float2half_rn(W[(size_t)k * COUT + n]);
    }
    __syncthreads();
#pragma unroll
    for (int r = 0; r < 4; r++) {
        int n = nt * 32 + ty + r * 8;
        int k = kt * 32 + tx;
        g_Wth[layer][n][k] = tile[tx][ty + r * 8];
    }
}

// ---------------- fused layers 1+2: persistent, 2 CTAs/SM -----------------
__global__ void __launch_bounds__(256, 2)
fused12_kernel(const float* __restrict__ support,
               const float* __restrict__ b1, const float* __restrict__ g1,
               const float* __restrict__ be1,
               const float* __restrict__ b2, const float* __restrict__ g2,
               const float* __restrict__ be2)
{
    constexpr int NC1 = CIN / KC12;    // 16
    constexpr int NC2 = COUT / KC12;   // 8

    extern __shared__ __align__(16) char smc[];
    const uint32_t sbase  = smem_u32(smc);
    const uint32_t bBase  = sbase + 2 * A1B;
    const uint32_t a2Base = sbase + A2OFF;
    char* a2c = smc + A2OFF;

    const int tid  = threadIdx.x;
    const int wid  = tid >> 5;
    const int lane = tid & 31;

    const __half* W1h = &g_Wth[0][0][0];
    const __half* W2h = &g_Wth[1][0][0];

    const int wr = (wid & 1) * 32;
    const int wc = (wid >> 1) * 64;
    const int qlane = lane & 3;

    const int a_r  = (lane & 15);
    const int a_kh = (lane >> 4) * 8;
    const int b_r  = ((lane >> 4) & 1) * 8 + (lane & 7);
    const int b_kh = ((lane >> 3) & 1) * 8;

    float4 vpipe[2];

#pragma unroll 1
    for (int blk = blockIdx.x; blk < NBLK12; blk += GRID_P) {
        const int rowBlk = blk * TM12;

        auto ldgA1 = [&](int kc) {
#pragma unroll
            for (int i = 0; i < 2; i++) {
                int s  = tid + i * 256;
                int r  = s >> 3;
                int c4 = (s & 7) * 4;
                vpipe[i] = __ldcs((const float4*)(support + (size_t)(rowBlk + r) * CIN + kc + c4));
            }
        };
        auto stsA1 = [&](int buf) {
            char* ab = smc + buf * A1B;
#pragma unroll
            for (int i = 0; i < 2; i++) {
                int s  = tid + i * 256;
                int r  = s >> 3;
                int c4 = (s & 7) * 4;
                uint32_t h[2];
                round4h(vpipe[i], h);
                *(uint2*)(ab + (r * AST12 + c4) * 2) = make_uint2(h[0], h[1]);
            }
        };
        auto cpB = [&](const __half* Wsrc, int kc, int buf) {
            uint32_t bh = bBase + buf * B12B;
#pragma unroll
            for (int i = 0; i < 4; i++) {
                int q   = tid + i * 256;
                int n   = q >> 2;
                int seg = q & 3;
                CP_ASYNC16CG(bh + (uint32_t)(n * AST12 * 2 + seg * 16),
                             Wsrc + (size_t)n * CIN + kc + seg * 8);
            }
        };

        float acc[2][8][4];
#pragma unroll
        for (int mi = 0; mi < 2; mi++)
#pragma unroll
            for (int j = 0; j < 8; j++)
#pragma unroll
                for (int c = 0; c < 4; c++) acc[mi][j][c] = 0.f;

        // ================= GEMM 1 (K=512, 16 chunks of 32) =================
        ldgA1(0);
        cpB(W1h, 0, 0);
        CP_COMMIT();
        stsA1(0);

#pragma unroll 1
        for (int c = 0; c < NC1; c++) {
            const int cb = c & 1;
            const bool more = (c + 1 < NC1);
            if (more) ldgA1((c + 1) * KC12);
            CP_WAIT0();
            __syncthreads();
            if (more) { cpB(W1h, (c + 1) * KC12, (c + 1) & 1); CP_COMMIT(); }

            const uint32_t aH = sbase + cb * A1B;
            const uint32_t bH = bBase + cb * B12B;
#pragma unroll
            for (int ks = 0; ks < 2; ks++) {
                const int k0 = ks * 16;
                uint32_t ah[2][4];
#pragma unroll
                for (int mi = 0; mi < 2; mi++)
                    LDSM4(ah[mi], aH + (uint32_t)((wr + mi * 16 + a_r) * AST12 + k0 + a_kh) * 2);
#pragma unroll
                for (int jp = 0; jp < 4; jp++) {
                    uint32_t bhr[4];
                    LDSM4(bhr, bH + (uint32_t)((wc + jp * 16 + b_r) * AST12 + k0 + b_kh) * 2);
#pragma unroll
                    for (int mi = 0; mi < 2; mi++)
#pragma unroll
                        for (int jj = 0; jj < 2; jj++)
                            MMA_F16(acc[mi][jp * 2 + jj], ah[mi],
                                    bhr[jj * 2], bhr[jj * 2 + 1]);
                }
            }
            if (more) stsA1((c + 1) & 1);
        }

        cpB(W2h, 0, 0);
        CP_COMMIT();

        // ---- epilogue 1: GN -> fp16 h1 tile into A2 ----
#pragma unroll
        for (int j = 0; j < 8; j++) {
            const int col = wc + j * 8 + 2 * qlane;
            const int ch  = (wid >> 1) * 2 + (j >> 2);
            const int kk  = (j & 3) * 8 + 2 * qlane;
            const float2 bb = *reinterpret_cast<const float2*>(b1 + col);
            const float2 gg = *reinterpret_cast<const float2*>(g1 + col);
            const float2 be = *reinterpret_cast<const float2*>(be1 + col);
#pragma unroll
            for (int mi = 0; mi < 2; mi++) {
                float y0, y1, y2, y3;
                gn8(acc[mi][j][0] + bb.x, acc[mi][j][1] + bb.y,
                    acc[mi][j][2] + bb.x, acc[mi][j][3] + bb.y, gg, be,
                    y0, y1, y2, y3);
                const int row0 = wr + mi * 16 + (lane >> 2);
                *(__half2*)(a2c + ch * A1B + (row0 * AST12 + kk) * 2)       = __floats2half2_rn(y0, y1);
                *(__half2*)(a2c + ch * A1B + ((row0 + 8) * AST12 + kk) * 2) = __floats2half2_rn(y2, y3);
            }
        }

#pragma unroll
        for (int mi = 0; mi < 2; mi++)
#pragma unroll
            for (int j = 0; j < 8; j++)
#pragma unroll
                for (int c = 0; c < 4; c++) acc[mi][j][c] = 0.f;

        __syncthreads();

        // ================= GEMM 2 (K=256, 8 chunks, A resident) ============
#pragma unroll 1
        for (int c = 0; c < NC2; c++) {
            const int cb = c & 1;
            const bool more = (c + 1 < NC2);
            CP_WAIT0();
            __syncthreads();
            if (more) { cpB(W2h, (c + 1) * KC12, (c + 1) & 1); CP_COMMIT(); }

            const uint32_t aH = a2Base + c * A1B;
            const uint32_t bH = bBase + cb * B12B;
#pragma unroll
            for (int ks = 0; ks < 2; ks++) {
                const int k0 = ks * 16;
                uint32_t ah[2][4];
#pragma unroll
                for (int mi = 0; mi < 2; mi++)
                    LDSM4(ah[mi], aH + (uint32_t)((wr + mi * 16 + a_r) * AST12 + k0 + a_kh) * 2);
#pragma unroll
                for (int jp = 0; jp < 4; jp++) {
                    uint32_t bhr[4];
                    LDSM4(bhr, bH + (uint32_t)((wc + jp * 16 + b_r) * AST12 + k0 + b_kh) * 2);
#pragma unroll
                    for (int mi = 0; mi < 2; mi++)
#pragma unroll
                        for (int jj = 0; jj < 2; jj++)
                            MMA_F16(acc[mi][jp * 2 + jj], ah[mi],
                                    bhr[jj * 2], bhr[jj * 2 + 1]);
                }
            }
        }

        // ---- epilogue 2: GN -> fp16 h2 to global ----
#pragma unroll
        for (int j = 0; j < 8; j++) {
            const int col = wc + j * 8 + 2 * qlane;
            const float2 bb = *reinterpret_cast<const float2*>(b2 + col);
            const float2 gg = *reinterpret_cast<const float2*>(g2 + col);
            const float2 be = *reinterpret_cast<const float2*>(be2 + col);
#pragma unroll
            for (int mi = 0; mi < 2; mi++) {
                float y0, y1, y2, y3;
                gn8(acc[mi][j][0] + bb.x, acc[mi][j][1] + bb.y,
                    acc[mi][j][2] + bb.x, acc[mi][j][3] + bb.y, gg, be,
                    y0, y1, y2, y3);
                const size_t row = (size_t)rowBlk + wr + mi * 16 + (lane >> 2);
                *(__half2*)(g_h2f + row * COUT + col)       = __floats2half2_rn(y0, y1);
                *(__half2*)(g_h2f + (row + 8) * COUT + col) = __floats2half2_rn(y2, y3);
            }
        }
        __syncthreads();   // protect smem buffers before next block's staging
    }
}

// ---------------- layer 3: persistent, 2 CTAs/SM --------------------------
__global__ void __launch_bounds__(256, 2)
layer3_kernel(const float* __restrict__ query,
              const float* __restrict__ b3, const float* __restrict__ g3,
              const float* __restrict__ be3,
              const int*   __restrict__ idx,
              float*       __restrict__ out)
{
    constexpr int NC = COUT / KC3;   // 4

    extern __shared__ __align__(16) char smc[];
    const uint32_t sbase = smem_u32(smc);
    const int tid  = threadIdx.x;
    const int wid  = tid >> 5;
    const int lane = tid & 31;

    const __half* W3h = &g_Wth[2][0][0];

    const int wr = (wid & 1) * 32;
    const int wc = (wid >> 1) * 64;
    const int qlane = lane & 3;

    const int a_r  = (lane & 15);
    const int a_kh = (lane >> 4) * 8;
    const int b_r  = ((lane >> 4) & 1) * 8 + (lane & 7);
    const int b_kh = ((lane >> 3) & 1) * 8;

    float4 vpipe[4];
    int    gidx[4];

#pragma unroll 1
    for (int blk = blockIdx.x; blk < NBLK3; blk += GRID_P) {
        const int rowBlk = blk * TILE_M3;

        // per-thread gather row ids (rows fixed per thread; reused all chunks)
#pragma unroll
        for (int i = 0; i < 4; i++) {
            int r    = (tid + i * 256) >> 4;
            int grow = rowBlk + r;
            gidx[i]  = (grow >> 16) * Mm + idx[grow];
        }

        auto ldgA = [&](int kc) {
#pragma unroll
            for (int i = 0; i < 4; i++) {
                int s  = tid + i * 256;
                int r  = s >> 4;
                int c4 = (s & 15) * 4;
                float4 q = __ldcs((const float4*)(query + (size_t)(rowBlk + r) * COUT + kc + c4));
                uint2 gv = *(const uint2*)(g_h2f + (size_t)gidx[i] * COUT + kc + c4);
                float2 ga = __half22float2(*reinterpret_cast<__half2*>(&gv.x));
                float2 gb = __half22float2(*reinterpret_cast<__half2*>(&gv.y));
                vpipe[i] = make_float4(q.x + ga.x, q.y + ga.y, q.z + gb.x, q.w + gb.y);
            }
        };
        auto stsA = [&](int buf) {
            char* ab = smc + buf * BUF3;
#pragma unroll
            for (int i = 0; i < 4; i++) {
                int s  = tid + i * 256;
                int r  = s >> 4;
                int c4 = (s & 15) * 4;
                uint32_t h[2];
                round4h(vpipe[i], h);
                *(uint2*)(ab + (r * ASTRE + c4) * 2) = make_uint2(h[0], h[1]);
            }
        };
        auto cpB = [&](int kc, int buf) {
            uint32_t bh = sbase + buf * BUF3 + A3_BYTES;
#pragma unroll
            for (int i = 0; i < 8; i++) {
                int q   = tid + i * 256;
                int n   = q >> 3;
                int seg = q & 7;
                CP_ASYNC16CG(bh + (uint32_t)(n * ASTRE * 2 + seg * 16),
                             W3h + (size_t)n * CIN + kc + seg * 8);
            }
        };

        float acc[2][8][4];
#pragma unroll
        for (int mi = 0; mi < 2; mi++)
#pragma unroll
            for (int j = 0; j < 8; j++)
#pragma unroll
                for (int c = 0; c < 4; c++) acc[mi][j][c] = 0.f;

        ldgA(0);
        cpB(0, 0);
        CP_COMMIT();
        stsA(0);

#pragma unroll 1
        for (int c = 0; c < NC; c++) {
            const int cb = c & 1;
            const bool more = (c + 1 < NC);
            if (more) ldgA((c + 1) * KC3);
            CP_WAIT0();
            __syncthreads();
            if (more) { cpB((c + 1) * KC3, (c + 1) & 1); CP_COMMIT(); }

            const uint32_t aH = sbase + cb * BUF3;
            const uint32_t bH = aH + A3_BYTES;
#pragma unroll
            for (int ks = 0; ks < 4; ks++) {
                const int k0 = ks * 16;
                uint32_t ah[2][4];
#pragma unroll
                for (int mi = 0; mi < 2; mi++)
                    LDSM4(ah[mi], aH + (uint32_t)((wr + mi * 16 + a_r) * ASTRE + k0 + a_kh) * 2);
#pragma unroll
                for (int jp = 0; jp < 4; jp++) {
                    uint32_t bhr[4];
                    LDSM4(bhr, bH + (uint32_t)((wc + jp * 16 + b_r) * ASTRE + k0 + b_kh) * 2);
#pragma unroll
                    for (int mi = 0; mi < 2; mi++)
#pragma unroll
                        for (int jj = 0; jj < 2; jj++)
                            MMA_F16(acc[mi][jp * 2 + jj], ah[mi],
                                    bhr[jj * 2], bhr[jj * 2 + 1]);
                }
            }
            if (more) stsA((c + 1) & 1);
        }

        // ---- epilogue: GN -> fp32 out (streaming stores) ----
#pragma unroll
        for (int j = 0; j < 8; j++) {
            const int col = wc + j * 8 + 2 * qlane;
            const float2 bb = *reinterpret_cast<const float2*>(b3 + col);
            const float2 gg = *reinterpret_cast<const float2*>(g3 + col);
            const float2 be = *reinterpret_cast<const float2*>(be3 + col);
#pragma unroll
            for (int mi = 0; mi < 2; mi++) {
                float y0, y1, y2, y3;
                gn8(acc[mi][j][0] + bb.x, acc[mi][j][1] + bb.y,
                    acc[mi][j][2] + bb.x, acc[mi][j][3] + bb.y, gg, be,
                    y0, y1, y2, y3);
                const size_t row = (size_t)rowBlk + wr + mi * 16 + (lane >> 2);
                __stcs(reinterpret_cast<float2*>(out + row * COUT + col),
                       make_float2(y0, y1));
                __stcs(reinterpret_cast<float2*>(out + (row + 8) * COUT + col),
                       make_float2(y2, y3));
            }
        }
        __syncthreads();   // protect A/B buffers before next block's staging
    }
}

extern "C" void kernel_launch(void* const* d_in, const int* in_sizes, int n_in,
                              void* d_out, int out_size)
{
    (void)in_sizes; (void)n_in; (void)out_size;
    const float* query   = (const float*)d_in[0];
    const float* support = (const float*)d_in[1];
    const int*   idx     = (const int*)d_in[2];
    const float* W1  = (const float*)d_in[3];
    const float* b1  = (const float*)d_in[4];
    const float* g1  = (const float*)d_in[5];
    const float* be1 = (const float*)d_in[6];
    const float* W2  = (const float*)d_in[7];
    const float* b2  = (const float*)d_in[8];
    const float* g2  = (const float*)d_in[9];
    const float* be2 = (const float*)d_in[10];
    const float* W3  = (const float*)d_in[11];
    const float* b3  = (const float*)d_in[12];
    const float* g3  = (const float*)d_in[13];
    const float* be3 = (const float*)d_in[14];
    float* out = (float*)d_out;

    split_w_all<<<256, 256>>>(W1, W2, W3);

    cudaFuncSetAttribute(fused12_kernel,
        cudaFuncAttributeMaxDynamicSharedMemorySize, (int)SMEM_F);
    cudaFuncSetAttribute(layer3_kernel,
        cudaFuncAttributeMaxDynamicSharedMemorySize, (int)SMEM_3);

    fused12_kernel<<<GRID_P, 256, SMEM_F>>>(
        support, b1, g1, be1, b2, g2, be2);
    layer3_kernel<<<GRID_P, 256, SMEM_3>>>(
        query, b3, g3, be3, idx, out);
}

// round 17
// speedup vs baseline: 1.0338x; 1.0338x over previous
#include <cuda_runtime.h>
#include <cuda_fp16.h>
#include <cstdint>

// ---------------------------------------------------------------------------
// Upsampling_77214922047593 — legacy mma.sync fp16 single-pass (sm_103 base).
//   fused12:  h2 = unary(unary(support @ W1) @ W2)   65536 rows (h1 in smem)
//   layer3:   out = unary((gather(h2)+query) @ W3)   262144 rows
// R16->R17: fused12 KC 32 -> 64 (chunk tails 24 -> 12) made to fit 2 CTAs/SM
// by ALIASING the resident h1 (A2) tile over the dead A1 double-buffer:
//   [A2 36.9KB (A1-dbl in its first 18.4KB)] [B-dbl 73.7KB] = 110.6KB/CTA.
// Extra __syncthreads() guards the alias. layer3 & split_w = R15 (best).
// ---------------------------------------------------------------------------

namespace {
constexpr int Mm   = 16384;
constexpr int CIN  = 512;
constexpr int COUT = 256;
constexpr float EPSv   = 1e-5f;
constexpr float SLOPEv = 0.1f;

constexpr int ROWS12 = 65536;
constexpr int ROWS3  = 262144;

// ---- fused12 geometry (TILE 64x256, KC=64, 2 CTAs/SM, aliased A2) ----
constexpr int TM12   = 64;
constexpr int KC12   = 64;
constexpr int AST12  = 72;                       // fp16 elems (144B rows)
constexpr int A1B    = TM12 * AST12 * 2;         // 9216
constexpr int B12B   = COUT * AST12 * 2;         // 36864
constexpr int A2SZ   = 4 * A1B;                  // 36864 (4 chunks of K=64)
constexpr int BOFF   = A2SZ;                     // B region follows A2
constexpr size_t SMEM_F = (size_t)A2SZ + 2 * B12B;  // 110592 (x2 = 221184)

// ---- layer3 geometry (TILE 64x256, KC=64, 2 CTAs/SM) — R15 ----
constexpr int TILE_M3 = 64;
constexpr int KC3     = 64;
constexpr int ASTRE   = 72;
constexpr int A3_BYTES = TILE_M3 * ASTRE * 2;    // 9216
constexpr int B3_BYTES = COUT * ASTRE * 2;       // 36864
constexpr int BUF3     = A3_BYTES + B3_BYTES;    // 46080
constexpr size_t SMEM_3 = 2 * (size_t)BUF3;      // 92160
} // namespace

__device__ __half g_h2f[(size_t)ROWS12 * COUT];     // fp16 h2 (32 MB)
__device__ __half g_Wth[3][COUT][CIN];              // rounded, transposed weights

// ---------------- helpers ----------------
__device__ __forceinline__ uint32_t smem_u32(const void* p) {
    uint32_t a;
    asm("{ .reg .u64 t; cvta.to.shared.u64 t, %1; cvt.u32.u64 %0, t; }"
        : "=r"(a) : "l"(p));
    return a;
}

#define LDSM4(r, addr)                                                         \
    asm volatile("ldmatrix.sync.aligned.m8n8.x4.shared.b16 {%0,%1,%2,%3}, [%4];" \
        : "=r"((r)[0]), "=r"((r)[1]), "=r"((r)[2]), "=r"((r)[3]) : "r"(addr))

#define MMA_F16(c, a, b0, b1)                                                  \
    asm volatile("mma.sync.aligned.m16n8k16.row.col.f32.f16.f16.f32 "          \
        "{%0,%1,%2,%3}, {%4,%5,%6,%7}, {%8,%9}, {%0,%1,%2,%3};"                \
        : "+f"((c)[0]), "+f"((c)[1]), "+f"((c)[2]), "+f"((c)[3])               \
        : "r"((a)[0]), "r"((a)[1]), "r"((a)[2]), "r"((a)[3]),                  \
          "r"(b0), "r"(b1))

#define CP_ASYNC16CG(dst, src)                                                 \
    asm volatile("cp.async.cg.shared.global [%0], [%1], 16;"                   \
        :: "r"(dst), "l"(src))
#define CP_COMMIT() asm volatile("cp.async.commit_group;" ::: "memory")
#define CP_WAIT0()  asm volatile("cp.async.wait_group 0;" ::: "memory")

__device__ __forceinline__ void round4h(float4 v, uint32_t h[2]) {
    __half2 h01 = __floats2half2_rn(v.x, v.y);
    __half2 h23 = __floats2half2_rn(v.z, v.w);
    h[0] = *reinterpret_cast<uint32_t*>(&h01);
    h[1] = *reinterpret_cast<uint32_t*>(&h23);
}

// GroupNorm-of-8 + affine + leaky-relu on one n8 tile's 4 acc values.
__device__ __forceinline__ void gn8(float v0, float v1, float v2, float v3,
                                    float2 gg, float2 be,
                                    float& y0, float& y1, float& y2, float& y3)
{
    float s0 = v0 + v1,           s1 = v2 + v3;
    float t0 = v0 * v0 + v1 * v1, t1 = v2 * v2 + v3 * v3;
    s0 += __shfl_xor_sync(0xffffffffu, s0, 1);
    s0 += __shfl_xor_sync(0xffffffffu, s0, 2);
    s1 += __shfl_xor_sync(0xffffffffu, s1, 1);
    s1 += __shfl_xor_sync(0xffffffffu, s1, 2);
    t0 += __shfl_xor_sync(0xffffffffu, t0, 1);
    t0 += __shfl_xor_sync(0xffffffffu, t0, 2);
    t1 += __shfl_xor_sync(0xffffffffu, t1, 1);
    t1 += __shfl_xor_sync(0xffffffffu, t1, 2);
    const float m0 = s0 * 0.125f, m1 = s1 * 0.125f;
    const float r0 = rsqrtf(fmaxf(t0 * 0.125f - m0 * m0, 0.f) + EPSv);
    const float r1 = rsqrtf(fmaxf(t1 * 0.125f - m1 * m1, 0.f) + EPSv);
    y0 = (v0 - m0) * r0 * gg.x + be.x;
    y1 = (v1 - m0) * r0 * gg.y + be.y;
    y2 = (v2 - m1) * r1 * gg.x + be.x;
    y3 = (v3 - m1) * r1 * gg.y + be.y;
    y0 = (y0 >= 0.f) ? y0 : SLOPEv * y0;
    y1 = (y1 >= 0.f) ? y1 : SLOPEv * y1;
    y2 = (y2 >= 0.f) ? y2 : SLOPEv * y2;
    y3 = (y3 >= 0.f) ? y3 : SLOPEv * y3;
}

// ---------------- weight prologue: coalesced smem-tile transpose -----------
__global__ void split_w_all(const float* __restrict__ W1,
                            const float* __restrict__ W2,
                            const float* __restrict__ W3)
{
    __shared__ __half tile[32][33];
    int b = blockIdx.x;            // 0..255
    const float* W;
    int layer, kt, nt;
    if (b < 128)      { W = W1; layer = 0; kt = b >> 3;        nt = b & 7; }
    else if (b < 192) { W = W2; layer = 1; kt = (b - 128) >> 3; nt = b & 7; }
    else              { W = W3; layer = 2; kt = (b - 192) >> 3; nt = b & 7; }

    const int tx = threadIdx.x & 31;
    const int ty = threadIdx.x >> 5;   // 0..7

#pragma unroll
    for (int r = 0; r < 4; r++) {
        int k = kt * 32 + ty + r * 8;
        int n = nt * 32 + tx;
        tile[ty + r * 8][tx] = __float2half_rn(W[(size_t)k * COUT + n]);
    }
    __syncthreads();
#pragma unroll
    for (int r = 0; r < 4; r++) {
        int n = nt * 32 + ty + r * 8;
        int k = kt * 32 + tx;
        g_Wth[layer][n][k] = tile[tx][ty + r * 8];
    }
}

// ---------------- fused layers 1+2: KC=64, aliased A2, 2 CTAs/SM ----------
__global__ void __launch_bounds__(256, 2)
fused12_kernel(const float* __restrict__ support,
               const float* __restrict__ b1, const float* __restrict__ g1,
               const float* __restrict__ be1,
               const float* __restrict__ b2, const float* __restrict__ g2,
               const float* __restrict__ be2)
{
    constexpr int NC1 = CIN / KC12;    // 8
    constexpr int NC2 = COUT / KC12;   // 4

    extern __shared__ __align__(16) char smc[];
    const uint32_t sbase  = smem_u32(smc);
    const uint32_t bBase  = sbase + BOFF;
    const uint32_t a2Base = sbase;          // A2 aliases A1 double-buffer
    char* a2c = smc;

    const int tid  = threadIdx.x;
    const int wid  = tid >> 5;
    const int lane = tid & 31;
    const int rowBlk = blockIdx.x * TM12;

    const __half* W1h = &g_Wth[0][0][0];
    const __half* W2h = &g_Wth[1][0][0];

    // A1: 64 rows x 64 fp32 = 1024 float4 / 256 thr = 4 each
    float4 vpipe[4];
    auto ldgA1 = [&](int kc) {
#pragma unroll
        for (int i = 0; i < 4; i++) {
            int s  = tid + i * 256;
            int r  = s >> 4;
            int c4 = (s & 15) * 4;
            vpipe[i] = __ldcs((const float4*)(support + (size_t)(rowBlk + r) * CIN + kc + c4));
        }
    };
    auto stsA1 = [&](int buf) {
        char* ab = smc + buf * A1B;
#pragma unroll
        for (int i = 0; i < 4; i++) {
            int s  = tid + i * 256;
            int r  = s >> 4;
            int c4 = (s & 15) * 4;
            uint32_t h[2];
            round4h(vpipe[i], h);
            *(uint2*)(ab + (r * AST12 + c4) * 2) = make_uint2(h[0], h[1]);
        }
    };
    // B: 256 n-rows x 8 16B-segs = 2048 segs / 256 thr = 8 each (cg, L2-only)
    auto cpB = [&](const __half* Wsrc, int kc, int buf) {
        uint32_t bh = bBase + buf * B12B;
#pragma unroll
        for (int i = 0; i < 8; i++) {
            int q   = tid + i * 256;
            int n   = q >> 3;
            int seg = q & 7;
            CP_ASYNC16CG(bh + (uint32_t)(n * AST12 * 2 + seg * 16),
                         Wsrc + (size_t)n * CIN + kc + seg * 8);
        }
    };

    // 8 warps = 2 m-groups x 4 n-groups, warp tile 32x64
    const int wr = (wid & 1) * 32;
    const int wc = (wid >> 1) * 64;
    const int qlane = lane & 3;

    float acc[2][8][4];
#pragma unroll
    for (int mi = 0; mi < 2; mi++)
#pragma unroll
        for (int j = 0; j < 8; j++)
#pragma unroll
            for (int c = 0; c < 4; c++) acc[mi][j][c] = 0.f;

    const int a_r  = (lane & 15);
    const int a_kh = (lane >> 4) * 8;
    const int b_r  = ((lane >> 4) & 1) * 8 + (lane & 7);
    const int b_kh = ((lane >> 3) & 1) * 8;

    // ================= GEMM 1 (K=512, 8 chunks of 64) =================
    ldgA1(0);
    cpB(W1h, 0, 0);
    CP_COMMIT();
    stsA1(0);

#pragma unroll 1
    for (int c = 0; c < NC1; c++) {
        const int cb = c & 1;
        const bool more = (c + 1 < NC1);
        if (more) ldgA1((c + 1) * KC12);
        CP_WAIT0();
        __syncthreads();
        if (more) { cpB(W1h, (c + 1) * KC12, (c + 1) & 1); CP_COMMIT(); }

        const uint32_t aH = sbase + cb * A1B;
        const uint32_t bH = bBase + cb * B12B;
#pragma unroll
        for (int ks = 0; ks < 4; ks++) {
            const int k0 = ks * 16;
            uint32_t ah[2][4];
#pragma unroll
            for (int mi = 0; mi < 2; mi++)
                LDSM4(ah[mi], aH + (uint32_t)((wr + mi * 16 + a_r) * AST12 + k0 + a_kh) * 2);
#pragma unroll
            for (int jp = 0; jp < 4; jp++) {
                uint32_t bhr[4];
                LDSM4(bhr, bH + (uint32_t)((wc + jp * 16 + b_r) * AST12 + k0 + b_kh) * 2);
#pragma unroll
                for (int mi = 0; mi < 2; mi++)
#pragma unroll
                    for (int jj = 0; jj < 2; jj++)
                        MMA_F16(acc[mi][jp * 2 + jj], ah[mi],
                                bhr[jj * 2], bhr[jj * 2 + 1]);
            }
        }
        if (more) stsA1((c + 1) & 1);
    }

    // all warps done reading A1 before epilogue overwrites it (alias guard)
    __syncthreads();

    cpB(W2h, 0, 0);      // prefetch W2 chunk 0 (B buf0: GEMM1 done with it)
    CP_COMMIT();

    // ---- epilogue 1: GN -> fp16 h1 tile into A2 (4 chunks of 64x64) ----
    // col = wc + j*8 + 2*qlane in [wc, wc+64) -> chunk = wid>>1,
    // within-chunk kk = j*8 + 2*qlane
#pragma unroll
    for (int j = 0; j < 8; j++) {
        const int col = wc + j * 8 + 2 * qlane;
        const int ch  = wid >> 1;
        const int kk  = j * 8 + 2 * qlane;
        const float2 bb = *reinterpret_cast<const float2*>(b1 + col);
        const float2 gg = *reinterpret_cast<const float2*>(g1 + col);
        const float2 be = *reinterpret_cast<const float2*>(be1 + col);
#pragma unroll
        for (int mi = 0; mi < 2; mi++) {
            float y0, y1, y2, y3;
            gn8(acc[mi][j][0] + bb.x, acc[mi][j][1] + bb.y,
                acc[mi][j][2] + bb.x, acc[mi][j][3] + bb.y, gg, be,
                y0, y1, y2, y3);
            const int row0 = wr + mi * 16 + (lane >> 2);
            *(__half2*)(a2c + ch * A1B + (row0 * AST12 + kk) * 2)       = __floats2half2_rn(y0, y1);
            *(__half2*)(a2c + ch * A1B + ((row0 + 8) * AST12 + kk) * 2) = __floats2half2_rn(y2, y3);
        }
    }

#pragma unroll
    for (int mi = 0; mi < 2; mi++)
#pragma unroll
        for (int j = 0; j < 8; j++)
#pragma unroll
            for (int c = 0; c < 4; c++) acc[mi][j][c] = 0.f;

    __syncthreads();   // A2 visible to all warps

    // ================= GEMM 2 (K=256, 4 chunks, A resident) =================
#pragma unroll 1
    for (int c = 0; c < NC2; c++) {
        const int cb = c & 1;
        const bool more = (c + 1 < NC2);
        CP_WAIT0();
        __syncthreads();
        if (more) { cpB(W2h, (c + 1) * KC12, (c + 1) & 1); CP_COMMIT(); }

        const uint32_t aH = a2Base + c * A1B;
        const uint32_t bH = bBase + cb * B12B;
#pragma unroll
        for (int ks = 0; ks < 4; ks++) {
            const int k0 = ks * 16;
            uint32_t ah[2][4];
#pragma unroll
            for (int mi = 0; mi < 2; mi++)
                LDSM4(ah[mi], aH + (uint32_t)((wr + mi * 16 + a_r) * AST12 + k0 + a_kh) * 2);
#pragma unroll
            for (int jp = 0; jp < 4; jp++) {
                uint32_t bhr[4];
                LDSM4(bhr, bH + (uint32_t)((wc + jp * 16 + b_r) * AST12 + k0 + b_kh) * 2);
#pragma unroll
                for (int mi = 0; mi < 2; mi++)
#pragma unroll
                    for (int jj = 0; jj < 2; jj++)
                        MMA_F16(acc[mi][jp * 2 + jj], ah[mi],
                                bhr[jj * 2], bhr[jj * 2 + 1]);
            }
        }
    }

    // ---- epilogue 2: GN -> fp16 h2 to global (stays L2-hot for gather) ----
#pragma unroll
    for (int j = 0; j < 8; j++) {
        const int col = wc + j * 8 + 2 * qlane;
        const float2 bb = *reinterpret_cast<const float2*>(b2 + col);
        const float2 gg = *reinterpret_cast<const float2*>(g2 + col);
        const float2 be = *reinterpret_cast<const float2*>(be2 + col);
#pragma unroll
        for (int mi = 0; mi < 2; mi++) {
            float y0, y1, y2, y3;
            gn8(acc[mi][j][0] + bb.x, acc[mi][j][1] + bb.y,
                acc[mi][j][2] + bb.x, acc[mi][j][3] + bb.y, gg, be,
                y0, y1, y2, y3);
            const size_t row = (size_t)rowBlk + wr + mi * 16 + (lane >> 2);
            *(__half2*)(g_h2f + row * COUT + col)       = __floats2half2_rn(y0, y1);
            *(__half2*)(g_h2f + (row + 8) * COUT + col) = __floats2half2_rn(y2, y3);
        }
    }
}

// ---------------- layer 3: TILE_M3=64, 256 thr, 2 CTAs/SM (R15) -----------
__global__ void __launch_bounds__(256, 2)
layer3_kernel(const float* __restrict__ query,
              const float* __restrict__ b3, const float* __restrict__ g3,
              const float* __restrict__ be3,
              const int*   __restrict__ idx,
              float*       __restrict__ out)
{
    constexpr int NC = COUT / KC3;   // 4

    extern __shared__ __align__(16) char smc[];
    __shared__ int s_grow[TILE_M3];

    const uint32_t sbase = smem_u32(smc);
    const int tid  = threadIdx.x;
    const int wid  = tid >> 5;
    const int lane = tid & 31;
    const int rowBlk = blockIdx.x * TILE_M3;

    const __half* W3h = &g_Wth[2][0][0];

    if (tid < TILE_M3) {
        int grow = rowBlk + tid;
        s_grow[tid] = (grow >> 16) * Mm + idx[grow];
    }
    __syncthreads();

    float4 vpipe[4];
    auto ldgA = [&](int kc) {
#pragma unroll
        for (int i = 0; i < 4; i++) {
            int s  = tid + i * 256;
            int r  = s >> 4;
            int c4 = (s & 15) * 4;
            float4 q = __ldcs((const float4*)(query + (size_t)(rowBlk + r) * COUT + kc + c4));
            uint2 gv = *(const uint2*)(g_h2f + (size_t)s_grow[r] * COUT + kc + c4);
            float2 ga = __half22float2(*reinterpret_cast<__half2*>(&gv.x));
            float2 gb = __half22float2(*reinterpret_cast<__half2*>(&gv.y));
            vpipe[i] = make_float4(q.x + ga.x, q.y + ga.y, q.z + gb.x, q.w + gb.y);
        }
    };
    auto stsA = [&](int buf) {
        char* ab = smc + buf * BUF3;
#pragma unroll
        for (int i = 0; i < 4; i++) {
            int s  = tid + i * 256;
            int r  = s >> 4;
            int c4 = (s & 15) * 4;
            uint32_t h[2];
            round4h(vpipe[i], h);
            *(uint2*)(ab + (r * ASTRE + c4) * 2) = make_uint2(h[0], h[1]);
        }
    };
    auto cpB = [&](int kc, int buf) {
        uint32_t bh = sbase + buf * BUF3 + A3_BYTES;
#pragma unroll
        for (int i = 0; i < 8; i++) {
            int q   = tid + i * 256;
            int n   = q >> 3;
            int seg = q & 7;
            CP_ASYNC16CG(bh + (uint32_t)(n * ASTRE * 2 + seg * 16),
                         W3h + (size_t)n * CIN + kc + seg * 8);
        }
    };

    const int wr = (wid & 1) * 32;
    const int wc = (wid >> 1) * 64;
    const int qlane = lane & 3;

    float acc[2][8][4];
#pragma unroll
    for (int mi = 0; mi < 2; mi++)
#pragma unroll
        for (int j = 0; j < 8; j++)
#pragma unroll
            for (int c = 0; c < 4; c++) acc[mi][j][c] = 0.f;

    const int a_r  = (lane & 15);
    const int a_kh = (lane >> 4) * 8;
    const int b_r  = ((lane >> 4) & 1) * 8 + (lane & 7);
    const int b_kh = ((lane >> 3) & 1) * 8;

    ldgA(0);
    cpB(0, 0);
    CP_COMMIT();
    stsA(0);

#pragma unroll 1
    for (int c = 0; c < NC; c++) {
        const int cb = c & 1;
        const bool more = (c + 1 < NC);
        if (more) ldgA((c + 1) * KC3);
        CP_WAIT0();
        __syncthreads();
        if (more) { cpB((c + 1) * KC3, (c + 1) & 1); CP_COMMIT(); }

        const uint32_t aH = sbase + cb * BUF3;
        const uint32_t bH = aH + A3_BYTES;
#pragma unroll
        for (int ks = 0; ks < 4; ks++) {
            const int k0 = ks * 16;
            uint32_t ah[2][4];
#pragma unroll
            for (int mi = 0; mi < 2; mi++)
                LDSM4(ah[mi], aH + (uint32_t)((wr + mi * 16 + a_r) * ASTRE + k0 + a_kh) * 2);
#pragma unroll
            for (int jp = 0; jp < 4; jp++) {
                uint32_t bhr[4];
                LDSM4(bhr, bH + (uint32_t)((wc + jp * 16 + b_r) * ASTRE + k0 + b_kh) * 2);
#pragma unroll
                for (int mi = 0; mi < 2; mi++)
#pragma unroll
                    for (int jj = 0; jj < 2; jj++)
                        MMA_F16(acc[mi][jp * 2 + jj], ah[mi],
                                bhr[jj * 2], bhr[jj * 2 + 1]);
            }
        }
        if (more) stsA((c + 1) & 1);
    }

    // ---- epilogue: GN -> fp32 out (streaming stores) ----
#pragma unroll
    for (int j = 0; j < 8; j++) {
        const int col = wc + j * 8 + 2 * qlane;
        const float2 bb = *reinterpret_cast<const float2*>(b3 + col);
        const float2 gg = *reinterpret_cast<const float2*>(g3 + col);
        const float2 be = *reinterpret_cast<const float2*>(be3 + col);
#pragma unroll
        for (int mi = 0; mi < 2; mi++) {
            float y0, y1, y2, y3;
            gn8(acc[mi][j][0] + bb.x, acc[mi][j][1] + bb.y,
                acc[mi][j][2] + bb.x, acc[mi][j][3] + bb.y, gg, be,
                y0, y1, y2, y3);
            const size_t row = (size_t)rowBlk + wr + mi * 16 + (lane >> 2);
            __stcs(reinterpret_cast<float2*>(out + row * COUT + col),
                   make_float2(y0, y1));
            __stcs(reinterpret_cast<float2*>(out + (row + 8) * COUT + col),
                   make_float2(y2, y3));
        }
    }
}

extern "C" void kernel_launch(void* const* d_in, const int* in_sizes, int n_in,
                              void* d_out, int out_size)
{
    (void)in_sizes; (void)n_in; (void)out_size;
    const float* query   = (const float*)d_in[0];
    const float* support = (const float*)d_in[1];
    const int*   idx     = (const int*)d_in[2];
    const float* W1  = (const float*)d_in[3];
    const float* b1  = (const float*)d_in[4];
    const float* g1  = (const float*)d_in[5];
    const float* be1 = (const float*)d_in[6];
    const float* W2  = (const float*)d_in[7];
    const float* b2  = (const float*)d_in[8];
    const float* g2  = (const float*)d_in[9];
    const float* be2 = (const float*)d_in[10];
    const float* W3  = (const float*)d_in[11];
    const float* b3  = (const float*)d_in[12];
    const float* g3  = (const float*)d_in[13];
    const float* be3 = (const float*)d_in[14];
    float* out = (float*)d_out;

    split_w_all<<<256, 256>>>(W1, W2, W3);

    cudaFuncSetAttribute(fused12_kernel,
        cudaFuncAttributeMaxDynamicSharedMemorySize, (int)SMEM_F);
    cudaFuncSetAttribute(layer3_kernel,
        cudaFuncAttributeMaxDynamicSharedMemorySize, (int)SMEM_3);

    fused12_kernel<<<ROWS12 / TM12, 256, SMEM_F>>>(
        support, b1, g1, be1, b2, g2, be2);
    layer3_kernel<<<ROWS3 / TILE_M3, 256, SMEM_3>>>(
        query, b3, g3, be3, idx, out);
}